// round 1
// baseline (speedup 1.0000x reference)
#include <cuda_runtime.h>
#include <math.h>
#include <stddef.h>

// ---------------------------------------------------------------------------
// Problem constants
// ---------------------------------------------------------------------------
#define B_TOK   16384
#define D_IN    512
#define D_OUT   64
#define H1      64
#define H2      32
#define GH      32
#define NEXP    6            // 2 shared + 4 group experts (flattened)
#define NGATE   3            // shared, group0, group1
#define NCAT    480          // 6*64 expert hiddens + 3*32 gate hiddens
#define LN_EPS  1e-5f

// Scratch (static device globals are the allowed scratch mechanism)
__device__ float g_Wc[D_IN * NCAT];      // packed layer-1 weights [k][n]
__device__ float g_bc[NCAT];             // packed layer-1 bias
__device__ float g_H[(size_t)B_TOK * NCAT];  // silu(v@Wc + b)  (31.5 MB)

// ---------------------------------------------------------------------------
// Kernel 0: pack layer-1 weights/biases into W_cat[512][480]
//   cols 0..383   : experts e=0..5 (e<2 shared, e>=2 group flat) x 64
//   cols 384..479 : gates s=0..2 (shared, g0, g1) x 32
// ---------------------------------------------------------------------------
__global__ void pack_kernel(const float* __restrict__ sw1, const float* __restrict__ sb1,
                            const float* __restrict__ gw1, const float* __restrict__ gb1,
                            const float* __restrict__ sgw1, const float* __restrict__ sgb1,
                            const float* __restrict__ ggw1, const float* __restrict__ ggb1) {
    int idx = blockIdx.x * 256 + threadIdx.x;
    if (idx < D_IN * NCAT) {
        int k = idx / NCAT, n = idx % NCAT;
        float w;
        if (n < 384) {
            int e = n >> 6, j = n & 63;
            w = (e < 2) ? sw1[((size_t)e * D_IN + k) * 64 + j]
                        : gw1[((size_t)(e - 2) * D_IN + k) * 64 + j];
        } else {
            int m = n - 384, s = m >> 5, j = m & 31;
            w = (s == 0) ? sgw1[k * 32 + j]
                         : ggw1[((size_t)(s - 1) * D_IN + k) * 32 + j];
        }
        g_Wc[idx] = w;
    }
    if (idx < NCAT) {
        int n = idx;
        float b;
        if (n < 384) {
            int e = n >> 6, j = n & 63;
            b = (e < 2) ? sb1[e * 64 + j] : gb1[(e - 2) * 64 + j];
        } else {
            int m = n - 384, s = m >> 5, j = m & 31;
            b = (s == 0) ? sgb1[j] : ggb1[(s - 1) * 32 + j];
        }
        g_bc[n] = b;
    }
}

// ---------------------------------------------------------------------------
// Kernel 1: H = silu(v @ Wc + bc)   [16384,512] x [512,480]
// Tiles: BM=128, BN=96, BK=16; 256 threads; 8x6 micro-tile per thread.
// ---------------------------------------------------------------------------
#define BM 128
#define BN 96
#define BK 16

__global__ __launch_bounds__(256) void gemm1_kernel(const float* __restrict__ V) {
    __shared__ float As[BK][BM];
    __shared__ float Bs[BK][BN];

    int tid = threadIdx.x;
    int bn = blockIdx.x * BN;
    int bm = blockIdx.y * BM;
    int tx = tid & 15, ty = tid >> 4;

    float acc[8][6];
#pragma unroll
    for (int i = 0; i < 8; i++)
#pragma unroll
        for (int j = 0; j < 6; j++) acc[i][j] = 0.f;

    int arow = tid >> 2;            // 0..63  (+64 second pass)
    int acol = (tid & 3) * 4;       // float4 within 16-wide k-chunk
    int bk   = tid >> 4;            // 0..15
    int boff = (tid & 15) * 6;      // 6 floats per thread per B row

    for (int k0 = 0; k0 < D_IN; k0 += BK) {
        // load A tile (transposed into As[k][m])
#pragma unroll
        for (int h = 0; h < 2; h++) {
            int r = arow + h * 64;
            float4 a4 = *(const float4*)(V + (size_t)(bm + r) * D_IN + k0 + acol);
            As[acol + 0][r] = a4.x;
            As[acol + 1][r] = a4.y;
            As[acol + 2][r] = a4.z;
            As[acol + 3][r] = a4.w;
        }
        // load B tile
        {
            const float* src = g_Wc + (size_t)(k0 + bk) * NCAT + bn + boff;
            float2 b0 = *(const float2*)(src);
            float2 b1 = *(const float2*)(src + 2);
            float2 b2 = *(const float2*)(src + 4);
            float* dst = &Bs[bk][boff];
            *(float2*)(dst)     = b0;
            *(float2*)(dst + 2) = b1;
            *(float2*)(dst + 4) = b2;
        }
        __syncthreads();

#pragma unroll
        for (int kk = 0; kk < BK; kk++) {
            float a[8], b[6];
#pragma unroll
            for (int i = 0; i < 8; i++) a[i] = As[kk][ty * 8 + i];
#pragma unroll
            for (int j = 0; j < 6; j++) b[j] = Bs[kk][tx * 6 + j];
#pragma unroll
            for (int i = 0; i < 8; i++)
#pragma unroll
                for (int j = 0; j < 6; j++) acc[i][j] += a[i] * b[j];
        }
        __syncthreads();
    }

    // epilogue: bias + silu, write H
#pragma unroll
    for (int i = 0; i < 8; i++) {
        size_t r = bm + ty * 8 + i;
#pragma unroll
        for (int j = 0; j < 6; j++) {
            int c = bn + tx * 6 + j;
            float x = acc[i][j] + g_bc[c];
            g_H[r * NCAT + c] = x / (1.f + expf(-x));
        }
    }
}

// ---------------------------------------------------------------------------
// Kernel 2: per-token tail. 256 threads = 8 warps, 4 tokens per warp per
// batch, 4 batches -> 128 tokens per CTA, grid 128.
// All layer-2/3 weights + LN params + gate-2 weights cached in smem.
// ---------------------------------------------------------------------------
__device__ __forceinline__ float wsum(float x) {
#pragma unroll
    for (int o = 16; o > 0; o >>= 1) x += __shfl_xor_sync(0xffffffffu, x, o);
    return x;
}

// smem layout sizes (floats)
#define SM_W2   (NEXP * H1 * H2)        // 12288
#define SM_W3   (NEXP * H2 * D_OUT)     // 12288
#define SM_B2   (NEXP * H2)             // 192
#define SM_B3   (NEXP * D_OUT)          // 384
#define SM_GM   (NEXP * D_OUT)          // 384
#define SM_BT   (NEXP * D_OUT)          // 384
#define SM_GW2  (NGATE * GH * 2)        // 192  layout [s][j][e]
#define SM_GB2  8                       // 6 used
#define SM_HS   (8 * 4 * NCAT)          // 15360
#define TAIL_SMEM_FLOATS (SM_W2 + SM_W3 + SM_B2 + SM_B3 + SM_GM + SM_BT + SM_GW2 + SM_GB2 + SM_HS)
#define TAIL_SMEM_BYTES  (TAIL_SMEM_FLOATS * 4)

__global__ __launch_bounds__(256) void tail_kernel(
    const float* __restrict__ sw2, const float* __restrict__ sb2,
    const float* __restrict__ sw3, const float* __restrict__ sb3,
    const float* __restrict__ sgam, const float* __restrict__ sbet,
    const float* __restrict__ sgw2, const float* __restrict__ sgb2,
    const float* __restrict__ gw2, const float* __restrict__ gb2,
    const float* __restrict__ gw3, const float* __restrict__ gb3,
    const float* __restrict__ ggam, const float* __restrict__ gbet,
    const float* __restrict__ ggw2, const float* __restrict__ ggb2,
    float* __restrict__ out) {
    extern __shared__ float sm[];
    float* W2s  = sm;
    float* W3s  = W2s + SM_W2;
    float* b2s  = W3s + SM_W3;
    float* b3s  = b2s + SM_B2;
    float* gms  = b3s + SM_B3;
    float* bts  = gms + SM_GM;
    float* gw2s = bts + SM_BT;
    float* gb2s = gw2s + SM_GW2;
    float* Hs   = gb2s + SM_GB2;

    int tid = threadIdx.x;
    // cooperative weight load (expert order: shared0, shared1, g0e0, g0e1, g1e0, g1e1)
    for (int i = tid; i < SM_W2; i += 256) {
        int e = i >> 11;
        W2s[i] = (e < 2) ? sw2[i] : gw2[i - 2 * 2048];
        W3s[i] = (e < 2) ? sw3[i] : gw3[i - 2 * 2048];
    }
    for (int i = tid; i < SM_B2; i += 256) b2s[i] = (i < 64) ? sb2[i] : gb2[i - 64];
    for (int i = tid; i < SM_B3; i += 256) {
        b3s[i] = (i < 128) ? sb3[i]  : gb3[i - 128];
        gms[i] = (i < 128) ? sgam[i] : ggam[i - 128];
        bts[i] = (i < 128) ? sbet[i] : gbet[i - 128];
    }
    for (int i = tid; i < SM_GW2; i += 256) {
        int s = i / 64, r = i % 64;   // [j][e] within slot, matches row-major [GH,2]
        gw2s[i] = (s == 0) ? sgw2[r] : ggw2[(s - 1) * 64 + r];
    }
    if (tid < 6) {
        int s = tid >> 1, e2 = tid & 1;
        gb2s[tid] = (s == 0) ? sgb2[e2] : ggb2[(s - 1) * 2 + e2];
    }
    __syncthreads();

    int warp = tid >> 5, lane = tid & 31;
    float* Hw = Hs + warp * (4 * NCAT);
    const unsigned FULL = 0xffffffffu;

    for (int batch = 0; batch < 4; batch++) {
        int t0 = blockIdx.x * 128 + batch * 32 + warp * 4;   // this warp's 4 tokens
        __syncwarp();
        for (int i = lane; i < 4 * NCAT; i += 32)
            Hw[i] = g_H[(size_t)(t0 + i / NCAT) * NCAT + (i % NCAT)];
        __syncwarp();

        // ---- gates: softmax over 2 experts per slot, per token ----
        float gwt[4][6];   // [t][slot*2 + e]
#pragma unroll
        for (int s = 0; s < 3; s++) {
            float w0j = gw2s[s * 64 + lane * 2];
            float w1j = gw2s[s * 64 + lane * 2 + 1];
            float bb0 = gb2s[s * 2], bb1 = gb2s[s * 2 + 1];
#pragma unroll
            for (int t = 0; t < 4; t++) {
                float hg = Hw[t * NCAT + 384 + s * 32 + lane];
                float l0 = wsum(hg * w0j) + bb0;
                float l1 = wsum(hg * w1j) + bb1;
                float m  = fmaxf(l0, l1);
                float e0 = expf(l0 - m), e1 = expf(l1 - m);
                float inv = 1.f / (e0 + e1);
                gwt[t][s * 2]     = e0 * inv;
                gwt[t][s * 2 + 1] = e1 * inv;
            }
        }

        float z[4][6];   // [t][plane*2 + half], planes: 0=group0,1=group1,2=shared
#pragma unroll
        for (int t = 0; t < 4; t++)
#pragma unroll
            for (int p = 0; p < 6; p++) z[t][p] = 0.f;

        for (int e = 0; e < 6; e++) {
            const float* w2c = W2s + e * 2048 + lane;     // column `lane` of W2_e
            float h2[4];
#pragma unroll
            for (int t = 0; t < 4; t++) h2[t] = b2s[e * 32 + lane];
#pragma unroll 8
            for (int i = 0; i < 64; i++) {
                float w = w2c[i * 32];
#pragma unroll
                for (int t = 0; t < 4; t++) h2[t] += Hw[t * NCAT + e * 64 + i] * w;
            }
#pragma unroll
            for (int t = 0; t < 4; t++) h2[t] = h2[t] / (1.f + expf(-h2[t]));

            float o0[4], o1[4];
#pragma unroll
            for (int t = 0; t < 4; t++) {
                o0[t] = b3s[e * 64 + lane];
                o1[t] = b3s[e * 64 + 32 + lane];
            }
#pragma unroll 4
            for (int i = 0; i < 32; i++) {
                float w0 = W3s[e * 2048 + i * 64 + lane];
                float w1 = W3s[e * 2048 + i * 64 + 32 + lane];
#pragma unroll
                for (int t = 0; t < 4; t++) {
                    float hv = __shfl_sync(FULL, h2[t], i);
                    o0[t] += hv * w0;
                    o1[t] += hv * w1;
                }
            }

            float gm0 = gms[e * 64 + lane], gm1 = gms[e * 64 + 32 + lane];
            float bt0 = bts[e * 64 + lane], bt1 = bts[e * 64 + 32 + lane];
            int slot  = (e < 2) ? 0 : ((e < 4) ? 1 : 2);
            int ei    = (e < 2) ? e : ((e - 2) & 1);
            int plane = (slot == 0) ? 2 : (slot - 1);
#pragma unroll
            for (int t = 0; t < 4; t++) {
                float mu  = wsum(o0[t] + o1[t]) * (1.f / 64.f);
                float d0  = o0[t] - mu, d1 = o1[t] - mu;
                float var = wsum(d0 * d0 + d1 * d1) * (1.f / 64.f);
                float x   = var + LN_EPS;
                float inv = rsqrtf(x);
                inv = inv * (1.5f - 0.5f * x * inv * inv);   // Newton refine
                float wg = gwt[t][slot * 2 + ei];
                z[t][plane * 2]     += wg * (gm0 * d0 * inv + bt0);
                z[t][plane * 2 + 1] += wg * (gm1 * d1 * inv + bt1);
            }
        }

#pragma unroll
        for (int t = 0; t < 4; t++) {
            size_t tt = (size_t)(t0 + t);
#pragma unroll
            for (int p = 0; p < 3; p++) {
                out[((size_t)p * B_TOK + tt) * 64 + lane]      = z[t][p * 2];
                out[((size_t)p * B_TOK + tt) * 64 + 32 + lane] = z[t][p * 2 + 1];
            }
        }
    }
}

// ---------------------------------------------------------------------------
// Launch
// ---------------------------------------------------------------------------
extern "C" void kernel_launch(void* const* d_in, const int* in_sizes, int n_in,
                              void* d_out, int out_size) {
    (void)in_sizes; (void)n_in; (void)out_size;
    const float* v    = (const float*)d_in[0];
    const float* sw1  = (const float*)d_in[1];
    const float* sb1  = (const float*)d_in[2];
    const float* sw2  = (const float*)d_in[3];
    const float* sb2  = (const float*)d_in[4];
    const float* sw3  = (const float*)d_in[5];
    const float* sb3  = (const float*)d_in[6];
    const float* sgam = (const float*)d_in[7];
    const float* sbet = (const float*)d_in[8];
    const float* sgw1 = (const float*)d_in[9];
    const float* sgb1 = (const float*)d_in[10];
    const float* sgw2 = (const float*)d_in[11];
    const float* sgb2 = (const float*)d_in[12];
    const float* gw1  = (const float*)d_in[13];
    const float* gb1  = (const float*)d_in[14];
    const float* gw2  = (const float*)d_in[15];
    const float* gb2  = (const float*)d_in[16];
    const float* gw3  = (const float*)d_in[17];
    const float* gb3  = (const float*)d_in[18];
    const float* ggam = (const float*)d_in[19];
    const float* gbet = (const float*)d_in[20];
    const float* ggw1 = (const float*)d_in[21];
    const float* ggb1 = (const float*)d_in[22];
    const float* ggw2 = (const float*)d_in[23];
    const float* ggb2 = (const float*)d_in[24];
    float* out = (float*)d_out;

    // pack layer-1 weights
    pack_kernel<<<(D_IN * NCAT + 255) / 256, 256>>>(sw1, sb1, gw1, gb1, sgw1, sgb1, ggw1, ggb1);

    // fused layer-1 GEMM + silu
    dim3 g1(NCAT / BN, B_TOK / BM);
    gemm1_kernel<<<g1, 256>>>(v);

    // tail (needs >48KB dynamic smem; idempotent attribute set each call)
    cudaFuncSetAttribute(tail_kernel, cudaFuncAttributeMaxDynamicSharedMemorySize, TAIL_SMEM_BYTES);
    tail_kernel<<<B_TOK / 128, 256, TAIL_SMEM_BYTES>>>(
        sw2, sb2, sw3, sb3, sgam, sbet, sgw2, sgb2,
        gw2, gb2, gw3, gb3, ggam, gbet, ggw2, ggb2, out);
}

// round 3
// speedup vs baseline: 1.6593x; 1.6593x over previous
#include <cuda_runtime.h>
#include <cuda_bf16.h>
#include <math.h>
#include <stddef.h>
#include <stdint.h>

// ---------------------------------------------------------------------------
// Problem constants
// ---------------------------------------------------------------------------
#define B_TOK   16384
#define D_IN    512
#define D_OUT   64
#define H1      64
#define H2      32
#define GH      32
#define NEXP    6
#define NGATE   3
#define NCAT    480
#define NCATP   512
#define LN_EPS  1e-5f

// ---------------------------------------------------------------------------
// Device scratch
// ---------------------------------------------------------------------------
__device__ __align__(16) __nv_bfloat16 g_vhi[(size_t)B_TOK * D_IN];
__device__ __align__(16) __nv_bfloat16 g_vlo[(size_t)B_TOK * D_IN];
__device__ __align__(16) __nv_bfloat16 g_wthi[NCATP * D_IN];   // [n][k]
__device__ __align__(16) __nv_bfloat16 g_wtlo[NCATP * D_IN];
__device__ float g_bc[NCATP];
__device__ __align__(16) float g_H[(size_t)B_TOK * NCATP];     // silu(v@W+b)

__device__ __forceinline__ uint32_t smem_u32(const void* p) {
    uint32_t a;
    asm("{ .reg .u64 t; cvta.to.shared.u64 t, %1; cvt.u32.u64 %0, t; }" : "=r"(a) : "l"(p));
    return a;
}

// ---------------------------------------------------------------------------
// Kernel: convert v -> bf16 hi/lo (error-free split)
// ---------------------------------------------------------------------------
__global__ __launch_bounds__(256) void conv_v_kernel(const float* __restrict__ v) {
    size_t i = ((size_t)blockIdx.x * 256 + threadIdx.x) * 4;
    float4 x = *(const float4*)(v + i);
    __nv_bfloat16 h0 = __float2bfloat16_rn(x.x), h1 = __float2bfloat16_rn(x.y);
    __nv_bfloat16 h2 = __float2bfloat16_rn(x.z), h3 = __float2bfloat16_rn(x.w);
    __nv_bfloat16 l0 = __float2bfloat16_rn(x.x - __bfloat162float(h0));
    __nv_bfloat16 l1 = __float2bfloat16_rn(x.y - __bfloat162float(h1));
    __nv_bfloat16 l2 = __float2bfloat16_rn(x.z - __bfloat162float(h2));
    __nv_bfloat16 l3 = __float2bfloat16_rn(x.w - __bfloat162float(h3));
    __nv_bfloat162* ph = (__nv_bfloat162*)(g_vhi + i);
    __nv_bfloat162* pl = (__nv_bfloat162*)(g_vlo + i);
    ph[0] = __nv_bfloat162(h0, h1); ph[1] = __nv_bfloat162(h2, h3);
    pl[0] = __nv_bfloat162(l0, l1); pl[1] = __nv_bfloat162(l2, l3);
}

// ---------------------------------------------------------------------------
// Kernel: pack transposed layer-1 weights [n][k] bf16 hi/lo + bias (padded)
// ---------------------------------------------------------------------------
__global__ __launch_bounds__(256) void pack_w_kernel(
    const float* __restrict__ sw1, const float* __restrict__ sb1,
    const float* __restrict__ gw1, const float* __restrict__ gb1,
    const float* __restrict__ sgw1, const float* __restrict__ sgb1,
    const float* __restrict__ ggw1, const float* __restrict__ ggb1) {
    int idx = blockIdx.x * 256 + threadIdx.x;   // over 512*512
    int n = idx >> 9, k = idx & 511;
    float w = 0.f;
    if (n < 384) {
        int e = n >> 6, j = n & 63;
        w = (e < 2) ? sw1[((size_t)e * D_IN + k) * 64 + j]
                    : gw1[((size_t)(e - 2) * D_IN + k) * 64 + j];
    } else if (n < 480) {
        int m = n - 384, s = m >> 5, j = m & 31;
        w = (s == 0) ? sgw1[k * 32 + j]
                     : ggw1[((size_t)(s - 1) * D_IN + k) * 32 + j];
    }
    __nv_bfloat16 hi = __float2bfloat16_rn(w);
    g_wthi[idx] = hi;
    g_wtlo[idx] = __float2bfloat16_rn(w - __bfloat162float(hi));
    if (idx < NCATP) {
        float b = 0.f;
        if (idx < 384) {
            int e = idx >> 6, j = idx & 63;
            b = (e < 2) ? sb1[e * 64 + j] : gb1[(e - 2) * 64 + j];
        } else if (idx < 480) {
            int m = idx - 384, s = m >> 5, j = m & 31;
            b = (s == 0) ? sgb1[j] : ggb1[(s - 1) * GH + j];
        }
        g_bc[idx] = b;
    }
}

// ---------------------------------------------------------------------------
// Kernel: H = silu(v @ W + b) via mma.sync bf16 split (3 passes), fp32 accum
// CTA 128x128, warps 2(M)x4(N) -> warp tile 64x32. K chunks of 64, cp.async.
// smem row stride = 72 bf16 = 144B (conflict-free ldmatrix).
// ---------------------------------------------------------------------------
#define KCH     64
#define RSTRIDE 144                       // bytes per smem row
#define OP_BYTES (128 * RSTRIDE)          // 18432 per operand-half
#define SMO_AHI 0
#define SMO_ALO (SMO_AHI + OP_BYTES)
#define SMO_BHI (SMO_ALO + OP_BYTES)
#define SMO_BLO (SMO_BHI + OP_BYTES)
#define SMO_BIAS (SMO_BLO + OP_BYTES)     // 73728
#define GEMM_SMEM (SMO_BIAS + 512)        // 128 bias floats

#define CPASYNC16(dst, src) \
    asm volatile("cp.async.cg.shared.global [%0], [%1], 16;" :: "r"(dst), "l"(src))

__device__ __forceinline__ void ldsm_x4(uint32_t* r, uint32_t a) {
    asm volatile("ldmatrix.sync.aligned.m8n8.x4.shared.b16 {%0,%1,%2,%3}, [%4];"
                 : "=r"(r[0]), "=r"(r[1]), "=r"(r[2]), "=r"(r[3]) : "r"(a));
}
__device__ __forceinline__ void mma_bf16(float* c, const uint32_t* a, uint32_t b0, uint32_t b1) {
    asm volatile(
        "mma.sync.aligned.m16n8k16.row.col.f32.bf16.bf16.f32 "
        "{%0,%1,%2,%3}, {%4,%5,%6,%7}, {%8,%9}, {%0,%1,%2,%3};"
        : "+f"(c[0]), "+f"(c[1]), "+f"(c[2]), "+f"(c[3])
        : "r"(a[0]), "r"(a[1]), "r"(a[2]), "r"(a[3]), "r"(b0), "r"(b1));
}

__global__ void __launch_bounds__(256, 2) gemm1_mma_kernel() {
    extern __shared__ char smem[];
    const uint32_t sb = smem_u32(smem);
    const int tid  = threadIdx.x;
    const int lane = tid & 31;
    const int warp = tid >> 5;
    const int wm = warp >> 2;            // 0..1 (M)
    const int wn = warp & 3;             // 0..3 (N)
    const int bm = blockIdx.y * 128;
    const int bn = blockIdx.x * 128;

    if (tid < 128) ((float*)(smem + SMO_BIAS))[tid] = g_bc[bn + tid];

    // per-thread cp.async geometry: 1024 16B rows-of-8 per operand, 4 per thread
    const int lr[4] = { (tid) >> 3, (tid + 256) >> 3, (tid + 512) >> 3, (tid + 768) >> 3 };
    const int lq = (tid & 7) * 16;       // byte offset within row

    // ldmatrix lane geometry
    const int mi = lane >> 3;
    const int a_row = (lane & 7) + ((mi & 1) << 3);
    const int a_kb  = (mi >= 2) ? 16 : 0;
    const int b_row = (lane & 7) + ((mi >= 2) ? 8 : 0);
    const int b_kb  = (mi & 1) ? 16 : 0;
    const uint32_t aAddr0 = sb + SMO_AHI + (wm * 64 + a_row) * RSTRIDE + a_kb;
    const uint32_t bAddr0 = sb + SMO_BHI + (wn * 32 + b_row) * RSTRIDE + b_kb;

    float acc[4][4][4];
#pragma unroll
    for (int i = 0; i < 4; i++)
#pragma unroll
        for (int j = 0; j < 4; j++)
#pragma unroll
            for (int u = 0; u < 4; u++) acc[i][j][u] = 0.f;

    for (int ch = 0; ch < 8; ch++) {
        const int k0 = ch * KCH;
        // async loads: A hi/lo + B hi/lo
#pragma unroll
        for (int j = 0; j < 4; j++) {
            int r = lr[j];
            uint32_t doff = r * RSTRIDE + lq;
            const __nv_bfloat16* sa = g_vhi  + (size_t)(bm + r) * D_IN + k0 + (lq >> 1);
            const __nv_bfloat16* sb_ = g_wthi + (size_t)(bn + r) * D_IN + k0 + (lq >> 1);
            CPASYNC16(sb + SMO_AHI + doff, sa);
            CPASYNC16(sb + SMO_ALO + doff, sa + (g_vlo - g_vhi));
            CPASYNC16(sb + SMO_BHI + doff, sb_);
            CPASYNC16(sb + SMO_BLO + doff, sb_ + (g_wtlo - g_wthi));
        }
        asm volatile("cp.async.commit_group;");
        asm volatile("cp.async.wait_group 0;");
        __syncthreads();

#pragma unroll
        for (int kt = 0; kt < 4; kt++) {
            const uint32_t ka = kt * 32;
            uint32_t ah[4][4], al[4][4], bh[2][4], bl[2][4];
#pragma unroll
            for (int mt = 0; mt < 4; mt++)
                ldsm_x4(ah[mt], aAddr0 + mt * (16 * RSTRIDE) + ka);
#pragma unroll
            for (int h = 0; h < 2; h++)
                ldsm_x4(bh[h], bAddr0 + h * (16 * RSTRIDE) + ka);
            // pass 1: Ahi * Bhi
#pragma unroll
            for (int mt = 0; mt < 4; mt++)
#pragma unroll
                for (int nt = 0; nt < 4; nt++)
                    mma_bf16(acc[mt][nt], ah[mt], bh[nt >> 1][(nt & 1) * 2], bh[nt >> 1][(nt & 1) * 2 + 1]);
            // pass 2: Ahi * Blo
#pragma unroll
            for (int h = 0; h < 2; h++)
                ldsm_x4(bl[h], bAddr0 + (SMO_BLO - SMO_BHI) + h * (16 * RSTRIDE) + ka);
#pragma unroll
            for (int mt = 0; mt < 4; mt++)
#pragma unroll
                for (int nt = 0; nt < 4; nt++)
                    mma_bf16(acc[mt][nt], ah[mt], bl[nt >> 1][(nt & 1) * 2], bl[nt >> 1][(nt & 1) * 2 + 1]);
            // pass 3: Alo * Bhi
#pragma unroll
            for (int mt = 0; mt < 4; mt++)
                ldsm_x4(al[mt], aAddr0 + (SMO_ALO - SMO_AHI) + mt * (16 * RSTRIDE) + ka);
#pragma unroll
            for (int mt = 0; mt < 4; mt++)
#pragma unroll
                for (int nt = 0; nt < 4; nt++)
                    mma_bf16(acc[mt][nt], al[mt], bh[nt >> 1][(nt & 1) * 2], bh[nt >> 1][(nt & 1) * 2 + 1]);
        }
        __syncthreads();
    }

    // epilogue: bias + silu -> g_H
    const float* bias = (const float*)(smem + SMO_BIAS);
#pragma unroll
    for (int mt = 0; mt < 4; mt++) {
        int row0 = bm + wm * 64 + mt * 16 + (lane >> 2);
#pragma unroll
        for (int nt = 0; nt < 4; nt++) {
            int cl = wn * 32 + nt * 8 + 2 * (lane & 3);
            float b0 = bias[cl], b1 = bias[cl + 1];
            float x0 = acc[mt][nt][0] + b0, x1 = acc[mt][nt][1] + b1;
            float x2 = acc[mt][nt][2] + b0, x3 = acc[mt][nt][3] + b1;
            float2 o01 = make_float2(x0 / (1.f + __expf(-x0)), x1 / (1.f + __expf(-x1)));
            float2 o23 = make_float2(x2 / (1.f + __expf(-x2)), x3 / (1.f + __expf(-x3)));
            *(float2*)(g_H + (size_t)row0 * NCATP + bn + cl)       = o01;
            *(float2*)(g_H + (size_t)(row0 + 8) * NCATP + bn + cl) = o23;
        }
    }
}

// ---------------------------------------------------------------------------
// Kernel: per-token tail (same as R1, H stride 512)
// ---------------------------------------------------------------------------
__device__ __forceinline__ float wsum(float x) {
#pragma unroll
    for (int o = 16; o > 0; o >>= 1) x += __shfl_xor_sync(0xffffffffu, x, o);
    return x;
}

#define SM_W2   (NEXP * H1 * H2)
#define SM_W3   (NEXP * H2 * D_OUT)
#define SM_B2   (NEXP * H2)
#define SM_B3   (NEXP * D_OUT)
#define SM_GM   (NEXP * D_OUT)
#define SM_BT   (NEXP * D_OUT)
#define SM_GW2  (NGATE * GH * 2)
#define SM_GB2  8
#define SM_HS   (8 * 4 * NCAT)
#define TAIL_SMEM_FLOATS (SM_W2 + SM_W3 + SM_B2 + SM_B3 + SM_GM + SM_BT + SM_GW2 + SM_GB2 + SM_HS)
#define TAIL_SMEM_BYTES  (TAIL_SMEM_FLOATS * 4)

__global__ __launch_bounds__(256) void tail_kernel(
    const float* __restrict__ sw2, const float* __restrict__ sb2,
    const float* __restrict__ sw3, const float* __restrict__ sb3,
    const float* __restrict__ sgam, const float* __restrict__ sbet,
    const float* __restrict__ sgw2, const float* __restrict__ sgb2,
    const float* __restrict__ gw2, const float* __restrict__ gb2,
    const float* __restrict__ gw3, const float* __restrict__ gb3,
    const float* __restrict__ ggam, const float* __restrict__ gbet,
    const float* __restrict__ ggw2, const float* __restrict__ ggb2,
    float* __restrict__ out) {
    extern __shared__ float sm[];
    float* W2s  = sm;
    float* W3s  = W2s + SM_W2;
    float* b2s  = W3s + SM_W3;
    float* b3s  = b2s + SM_B2;
    float* gms  = b3s + SM_B3;
    float* bts  = gms + SM_GM;
    float* gw2s = bts + SM_BT;
    float* gb2s = gw2s + SM_GW2;
    float* Hs   = gb2s + SM_GB2;

    int tid = threadIdx.x;
    for (int i = tid; i < SM_W2; i += 256) {
        int e = i >> 11;
        W2s[i] = (e < 2) ? sw2[i] : gw2[i - 2 * 2048];
        W3s[i] = (e < 2) ? sw3[i] : gw3[i - 2 * 2048];
    }
    for (int i = tid; i < SM_B2; i += 256) b2s[i] = (i < 64) ? sb2[i] : gb2[i - 64];
    for (int i = tid; i < SM_B3; i += 256) {
        b3s[i] = (i < 128) ? sb3[i]  : gb3[i - 128];
        gms[i] = (i < 128) ? sgam[i] : ggam[i - 128];
        bts[i] = (i < 128) ? sbet[i] : gbet[i - 128];
    }
    for (int i = tid; i < SM_GW2; i += 256) {
        int s = i / 64, r = i % 64;
        gw2s[i] = (s == 0) ? sgw2[r] : ggw2[(s - 1) * 64 + r];
    }
    if (tid < 6) {
        int s = tid >> 1, e2 = tid & 1;
        gb2s[tid] = (s == 0) ? sgb2[e2] : ggb2[(s - 1) * 2 + e2];
    }
    __syncthreads();

    int warp = tid >> 5, lane = tid & 31;
    float* Hw = Hs + warp * (4 * NCAT);
    const unsigned FULL = 0xffffffffu;

    for (int batch = 0; batch < 4; batch++) {
        int t0 = blockIdx.x * 128 + batch * 32 + warp * 4;
        __syncwarp();
        for (int i = lane; i < 4 * NCAT; i += 32)
            Hw[i] = g_H[(size_t)(t0 + i / NCAT) * NCATP + (i % NCAT)];
        __syncwarp();

        float gwt[4][6];
#pragma unroll
        for (int s = 0; s < 3; s++) {
            float w0j = gw2s[s * 64 + lane * 2];
            float w1j = gw2s[s * 64 + lane * 2 + 1];
            float bb0 = gb2s[s * 2], bb1 = gb2s[s * 2 + 1];
#pragma unroll
            for (int t = 0; t < 4; t++) {
                float hg = Hw[t * NCAT + 384 + s * 32 + lane];
                float l0 = wsum(hg * w0j) + bb0;
                float l1 = wsum(hg * w1j) + bb1;
                float m  = fmaxf(l0, l1);
                float e0 = expf(l0 - m), e1 = expf(l1 - m);
                float inv = 1.f / (e0 + e1);
                gwt[t][s * 2]     = e0 * inv;
                gwt[t][s * 2 + 1] = e1 * inv;
            }
        }

        float z[4][6];
#pragma unroll
        for (int t = 0; t < 4; t++)
#pragma unroll
            for (int p = 0; p < 6; p++) z[t][p] = 0.f;

        for (int e = 0; e < 6; e++) {
            const float* w2c = W2s + e * 2048 + lane;
            float h2[4];
#pragma unroll
            for (int t = 0; t < 4; t++) h2[t] = b2s[e * 32 + lane];
#pragma unroll 8
            for (int i = 0; i < 64; i++) {
                float w = w2c[i * 32];
#pragma unroll
                for (int t = 0; t < 4; t++) h2[t] += Hw[t * NCAT + e * 64 + i] * w;
            }
#pragma unroll
            for (int t = 0; t < 4; t++) h2[t] = h2[t] / (1.f + expf(-h2[t]));

            float o0[4], o1[4];
#pragma unroll
            for (int t = 0; t < 4; t++) {
                o0[t] = b3s[e * 64 + lane];
                o1[t] = b3s[e * 64 + 32 + lane];
            }
#pragma unroll 4
            for (int i = 0; i < 32; i++) {
                float w0 = W3s[e * 2048 + i * 64 + lane];
                float w1 = W3s[e * 2048 + i * 64 + 32 + lane];
#pragma unroll
                for (int t = 0; t < 4; t++) {
                    float hv = __shfl_sync(FULL, h2[t], i);
                    o0[t] += hv * w0;
                    o1[t] += hv * w1;
                }
            }

            float gm0 = gms[e * 64 + lane], gm1 = gms[e * 64 + 32 + lane];
            float bt0 = bts[e * 64 + lane], bt1 = bts[e * 64 + 32 + lane];
            int slot  = (e < 2) ? 0 : ((e < 4) ? 1 : 2);
            int ei    = (e < 2) ? e : ((e - 2) & 1);
            int plane = (slot == 0) ? 2 : (slot - 1);
#pragma unroll
            for (int t = 0; t < 4; t++) {
                float mu  = wsum(o0[t] + o1[t]) * (1.f / 64.f);
                float d0  = o0[t] - mu, d1 = o1[t] - mu;
                float var = wsum(d0 * d0 + d1 * d1) * (1.f / 64.f);
                float x   = var + LN_EPS;
                float inv = rsqrtf(x);
                inv = inv * (1.5f - 0.5f * x * inv * inv);
                float wg = gwt[t][slot * 2 + ei];
                z[t][plane * 2]     += wg * (gm0 * d0 * inv + bt0);
                z[t][plane * 2 + 1] += wg * (gm1 * d1 * inv + bt1);
            }
        }

#pragma unroll
        for (int t = 0; t < 4; t++) {
            size_t tt = (size_t)(t0 + t);
#pragma unroll
            for (int p = 0; p < 3; p++) {
                out[((size_t)p * B_TOK + tt) * 64 + lane]      = z[t][p * 2];
                out[((size_t)p * B_TOK + tt) * 64 + 32 + lane] = z[t][p * 2 + 1];
            }
        }
    }
}

// ---------------------------------------------------------------------------
// Launch
// ---------------------------------------------------------------------------
extern "C" void kernel_launch(void* const* d_in, const int* in_sizes, int n_in,
                              void* d_out, int out_size) {
    (void)in_sizes; (void)n_in; (void)out_size;
    const float* v    = (const float*)d_in[0];
    const float* sw1  = (const float*)d_in[1];
    const float* sb1  = (const float*)d_in[2];
    const float* sw2  = (const float*)d_in[3];
    const float* sb2  = (const float*)d_in[4];
    const float* sw3  = (const float*)d_in[5];
    const float* sb3  = (const float*)d_in[6];
    const float* sgam = (const float*)d_in[7];
    const float* sbet = (const float*)d_in[8];
    const float* sgw1 = (const float*)d_in[9];
    const float* sgb1 = (const float*)d_in[10];
    const float* sgw2 = (const float*)d_in[11];
    const float* sgb2 = (const float*)d_in[12];
    const float* gw1  = (const float*)d_in[13];
    const float* gb1  = (const float*)d_in[14];
    const float* gw2  = (const float*)d_in[15];
    const float* gb2  = (const float*)d_in[16];
    const float* gw3  = (const float*)d_in[17];
    const float* gb3  = (const float*)d_in[18];
    const float* ggam = (const float*)d_in[19];
    const float* gbet = (const float*)d_in[20];
    const float* ggw1 = (const float*)d_in[21];
    const float* ggb1 = (const float*)d_in[22];
    const float* ggw2 = (const float*)d_in[23];
    const float* ggb2 = (const float*)d_in[24];
    float* out = (float*)d_out;

    conv_v_kernel<<<(B_TOK * D_IN / 4 + 255) / 256, 256>>>(v);
    pack_w_kernel<<<(NCATP * D_IN + 255) / 256, 256>>>(sw1, sb1, gw1, gb1, sgw1, sgb1, ggw1, ggb1);

    cudaFuncSetAttribute(gemm1_mma_kernel, cudaFuncAttributeMaxDynamicSharedMemorySize, GEMM_SMEM);
    dim3 g1(NCATP / 128, B_TOK / 128);
    gemm1_mma_kernel<<<g1, 256, GEMM_SMEM>>>();

    cudaFuncSetAttribute(tail_kernel, cudaFuncAttributeMaxDynamicSharedMemorySize, TAIL_SMEM_BYTES);
    tail_kernel<<<B_TOK / 128, 256, TAIL_SMEM_BYTES>>>(
        sw2, sb2, sw3, sb3, sgam, sbet, sgw2, sgb2,
        gw2, gb2, gw3, gb3, ggam, gbet, ggw2, ggb2, out);
}

// round 4
// speedup vs baseline: 1.8774x; 1.1314x over previous
#include <cuda_runtime.h>
#include <cuda_bf16.h>
#include <math.h>
#include <stddef.h>
#include <stdint.h>

// ---------------------------------------------------------------------------
// Problem constants
// ---------------------------------------------------------------------------
#define B_TOK   16384
#define D_IN    512
#define D_OUT   64
#define H1      64
#define H2      32
#define GH      32
#define NEXP    6
#define NGATE   3
#define NCAT    480
#define NCATP   512
#define LN_EPS  1e-5f

// ---------------------------------------------------------------------------
// Device scratch
// ---------------------------------------------------------------------------
__device__ __align__(16) __nv_bfloat16 g_vhi[(size_t)B_TOK * D_IN];
__device__ __align__(16) __nv_bfloat16 g_vlo[(size_t)B_TOK * D_IN];
__device__ __align__(16) __nv_bfloat16 g_wthi[NCATP * D_IN];   // [n][k]
__device__ __align__(16) __nv_bfloat16 g_wtlo[NCATP * D_IN];
__device__ float g_bc[NCATP];
__device__ __align__(16) float g_HT[(size_t)NCATP * B_TOK];    // H transposed [col][token]
__device__ __align__(16) float g_EO[(size_t)NEXP * B_TOK * D_OUT]; // gate-scaled expert outs

__device__ __forceinline__ uint32_t smem_u32(const void* p) {
    uint32_t a;
    asm("{ .reg .u64 t; cvta.to.shared.u64 t, %1; cvt.u32.u64 %0, t; }" : "=r"(a) : "l"(p));
    return a;
}

// ---------------------------------------------------------------------------
// Kernel: convert v -> bf16 hi/lo (error-free split)
// ---------------------------------------------------------------------------
__global__ __launch_bounds__(256) void conv_v_kernel(const float* __restrict__ v) {
    size_t i = ((size_t)blockIdx.x * 256 + threadIdx.x) * 4;
    float4 x = *(const float4*)(v + i);
    __nv_bfloat16 h0 = __float2bfloat16_rn(x.x), h1 = __float2bfloat16_rn(x.y);
    __nv_bfloat16 h2 = __float2bfloat16_rn(x.z), h3 = __float2bfloat16_rn(x.w);
    __nv_bfloat16 l0 = __float2bfloat16_rn(x.x - __bfloat162float(h0));
    __nv_bfloat16 l1 = __float2bfloat16_rn(x.y - __bfloat162float(h1));
    __nv_bfloat16 l2 = __float2bfloat16_rn(x.z - __bfloat162float(h2));
    __nv_bfloat16 l3 = __float2bfloat16_rn(x.w - __bfloat162float(h3));
    __nv_bfloat162* ph = (__nv_bfloat162*)(g_vhi + i);
    __nv_bfloat162* pl = (__nv_bfloat162*)(g_vlo + i);
    ph[0] = __nv_bfloat162(h0, h1); ph[1] = __nv_bfloat162(h2, h3);
    pl[0] = __nv_bfloat162(l0, l1); pl[1] = __nv_bfloat162(l2, l3);
}

// ---------------------------------------------------------------------------
// Kernel: pack transposed layer-1 weights [n][k] bf16 hi/lo + bias (padded)
// ---------------------------------------------------------------------------
__global__ __launch_bounds__(256) void pack_w_kernel(
    const float* __restrict__ sw1, const float* __restrict__ sb1,
    const float* __restrict__ gw1, const float* __restrict__ gb1,
    const float* __restrict__ sgw1, const float* __restrict__ sgb1,
    const float* __restrict__ ggw1, const float* __restrict__ ggb1) {
    int idx = blockIdx.x * 256 + threadIdx.x;   // over 512*512
    int n = idx >> 9, k = idx & 511;
    float w = 0.f;
    if (n < 384) {
        int e = n >> 6, j = n & 63;
        w = (e < 2) ? sw1[((size_t)e * D_IN + k) * 64 + j]
                    : gw1[((size_t)(e - 2) * D_IN + k) * 64 + j];
    } else if (n < 480) {
        int m = n - 384, s = m >> 5, j = m & 31;
        w = (s == 0) ? sgw1[k * 32 + j]
                     : ggw1[((size_t)(s - 1) * D_IN + k) * 32 + j];
    }
    __nv_bfloat16 hi = __float2bfloat16_rn(w);
    g_wthi[idx] = hi;
    g_wtlo[idx] = __float2bfloat16_rn(w - __bfloat162float(hi));
    if (idx < NCATP) {
        float b = 0.f;
        if (idx < 384) {
            int e = idx >> 6, j = idx & 63;
            b = (e < 2) ? sb1[e * 64 + j] : gb1[(e - 2) * 64 + j];
        } else if (idx < 480) {
            int m = idx - 384, s = m >> 5, j = m & 31;
            b = (s == 0) ? sgb1[j] : ggb1[(s - 1) * GH + j];
        }
        g_bc[idx] = b;
    }
}

// ---------------------------------------------------------------------------
// Kernel: H^T = silu(v @ W + b)^T via mma.sync bf16 split (3 passes)
// CTA 128x128, warps 2(M)x4(N). K chunks of 64, cp.async.
// Epilogue stages through smem and writes g_HT coalesced (column-major).
// ---------------------------------------------------------------------------
#define KCH     64
#define RSTRIDE 144
#define OP_BYTES (128 * RSTRIDE)
#define SMO_AHI 0
#define SMO_ALO (SMO_AHI + OP_BYTES)
#define SMO_BHI (SMO_ALO + OP_BYTES)
#define SMO_BLO (SMO_BHI + OP_BYTES)
#define SMO_BIAS (SMO_BLO + OP_BYTES)     // 73728
#define GEMM_SMEM (SMO_BIAS + 512)
#define STG_STRIDE 136                    // floats, stage[col][row]

#define CPASYNC16(dst, src) \
    asm volatile("cp.async.cg.shared.global [%0], [%1], 16;" :: "r"(dst), "l"(src))

__device__ __forceinline__ void ldsm_x4(uint32_t* r, uint32_t a) {
    asm volatile("ldmatrix.sync.aligned.m8n8.x4.shared.b16 {%0,%1,%2,%3}, [%4];"
                 : "=r"(r[0]), "=r"(r[1]), "=r"(r[2]), "=r"(r[3]) : "r"(a));
}
__device__ __forceinline__ void mma_bf16(float* c, const uint32_t* a, uint32_t b0, uint32_t b1) {
    asm volatile(
        "mma.sync.aligned.m16n8k16.row.col.f32.bf16.bf16.f32 "
        "{%0,%1,%2,%3}, {%4,%5,%6,%7}, {%8,%9}, {%0,%1,%2,%3};"
        : "+f"(c[0]), "+f"(c[1]), "+f"(c[2]), "+f"(c[3])
        : "r"(a[0]), "r"(a[1]), "r"(a[2]), "r"(a[3]), "r"(b0), "r"(b1));
}

__global__ void __launch_bounds__(256, 2) gemm1_mma_kernel() {
    extern __shared__ char smem[];
    const uint32_t sb = smem_u32(smem);
    const int tid  = threadIdx.x;
    const int lane = tid & 31;
    const int warp = tid >> 5;
    const int wm = warp >> 2;
    const int wn = warp & 3;
    const int bm = blockIdx.y * 128;
    const int bn = blockIdx.x * 128;

    if (tid < 128) ((float*)(smem + SMO_BIAS))[tid] = g_bc[bn + tid];

    const int lr[4] = { (tid) >> 3, (tid + 256) >> 3, (tid + 512) >> 3, (tid + 768) >> 3 };
    const int lq = (tid & 7) * 16;

    const int mi = lane >> 3;
    const int a_row = (lane & 7) + ((mi & 1) << 3);
    const int a_kb  = (mi >= 2) ? 16 : 0;
    const int b_row = (lane & 7) + ((mi >= 2) ? 8 : 0);
    const int b_kb  = (mi & 1) ? 16 : 0;
    const uint32_t aAddr0 = sb + SMO_AHI + (wm * 64 + a_row) * RSTRIDE + a_kb;
    const uint32_t bAddr0 = sb + SMO_BHI + (wn * 32 + b_row) * RSTRIDE + b_kb;

    float acc[4][4][4];
#pragma unroll
    for (int i = 0; i < 4; i++)
#pragma unroll
        for (int j = 0; j < 4; j++)
#pragma unroll
            for (int u = 0; u < 4; u++) acc[i][j][u] = 0.f;

    for (int ch = 0; ch < 8; ch++) {
        const int k0 = ch * KCH;
#pragma unroll
        for (int j = 0; j < 4; j++) {
            int r = lr[j];
            uint32_t doff = r * RSTRIDE + lq;
            const __nv_bfloat16* sa  = g_vhi  + (size_t)(bm + r) * D_IN + k0 + (lq >> 1);
            const __nv_bfloat16* sb_ = g_wthi + (size_t)(bn + r) * D_IN + k0 + (lq >> 1);
            CPASYNC16(sb + SMO_AHI + doff, sa);
            CPASYNC16(sb + SMO_ALO + doff, sa + (g_vlo - g_vhi));
            CPASYNC16(sb + SMO_BHI + doff, sb_);
            CPASYNC16(sb + SMO_BLO + doff, sb_ + (g_wtlo - g_wthi));
        }
        asm volatile("cp.async.commit_group;");
        asm volatile("cp.async.wait_group 0;");
        __syncthreads();

#pragma unroll
        for (int kt = 0; kt < 4; kt++) {
            const uint32_t ka = kt * 32;
            uint32_t ah[4][4], al[4][4], bh[2][4], bl[2][4];
#pragma unroll
            for (int mt = 0; mt < 4; mt++)
                ldsm_x4(ah[mt], aAddr0 + mt * (16 * RSTRIDE) + ka);
#pragma unroll
            for (int h = 0; h < 2; h++)
                ldsm_x4(bh[h], bAddr0 + h * (16 * RSTRIDE) + ka);
#pragma unroll
            for (int mt = 0; mt < 4; mt++)
#pragma unroll
                for (int nt = 0; nt < 4; nt++)
                    mma_bf16(acc[mt][nt], ah[mt], bh[nt >> 1][(nt & 1) * 2], bh[nt >> 1][(nt & 1) * 2 + 1]);
#pragma unroll
            for (int h = 0; h < 2; h++)
                ldsm_x4(bl[h], bAddr0 + (SMO_BLO - SMO_BHI) + h * (16 * RSTRIDE) + ka);
#pragma unroll
            for (int mt = 0; mt < 4; mt++)
#pragma unroll
                for (int nt = 0; nt < 4; nt++)
                    mma_bf16(acc[mt][nt], ah[mt], bl[nt >> 1][(nt & 1) * 2], bl[nt >> 1][(nt & 1) * 2 + 1]);
#pragma unroll
            for (int mt = 0; mt < 4; mt++)
                ldsm_x4(al[mt], aAddr0 + (SMO_ALO - SMO_AHI) + mt * (16 * RSTRIDE) + ka);
#pragma unroll
            for (int mt = 0; mt < 4; mt++)
#pragma unroll
                for (int nt = 0; nt < 4; nt++)
                    mma_bf16(acc[mt][nt], al[mt], bh[nt >> 1][(nt & 1) * 2], bh[nt >> 1][(nt & 1) * 2 + 1]);
        }
        __syncthreads();
    }

    // Epilogue: bias + silu -> smem stage [col][row] -> coalesced g_HT writes
    {
        float* stg = (float*)smem;
        const float* bias = (const float*)(smem + SMO_BIAS);
#pragma unroll
        for (int mt = 0; mt < 4; mt++) {
#pragma unroll
            for (int nt = 0; nt < 4; nt++) {
#pragma unroll
                for (int u = 0; u < 4; u++) {
                    int row = wm * 64 + mt * 16 + (lane >> 2) + ((u >> 1) << 3);
                    int col = wn * 32 + nt * 8 + 2 * (lane & 3) + (u & 1);
                    float x = acc[mt][nt][u] + bias[col];
                    stg[col * STG_STRIDE + row] = x / (1.f + __expf(-x));
                }
            }
        }
        __syncthreads();
#pragma unroll
        for (int cl = 0; cl < 16; cl++) {
            int col = warp * 16 + cl;
            int gc = bn + col;
            if (gc < NCAT) {
                float4 val = *(float4*)&stg[col * STG_STRIDE + lane * 4];
                *(float4*)(g_HT + (size_t)gc * B_TOK + bm + lane * 4) = val;
            }
        }
    }
}

// ---------------------------------------------------------------------------
// Kernel: tail2 — token-per-thread, expert-per-CTA. No shuffles.
// grid (B/128, 6), 128 threads. Writes gate-scaled LN output to g_EO.
// ---------------------------------------------------------------------------
__global__ __launch_bounds__(128) void tail2_kernel(
    const float* __restrict__ sw2, const float* __restrict__ sb2,
    const float* __restrict__ sw3, const float* __restrict__ sb3,
    const float* __restrict__ sgam, const float* __restrict__ sbet,
    const float* __restrict__ sgw2, const float* __restrict__ sgb2,
    const float* __restrict__ gw2, const float* __restrict__ gb2,
    const float* __restrict__ gw3, const float* __restrict__ gb3,
    const float* __restrict__ ggam, const float* __restrict__ gbet,
    const float* __restrict__ ggw2, const float* __restrict__ ggb2) {
    __shared__ float w2s[H1 * H2];       // [i][j] 2048
    __shared__ float w3s[H2 * D_OUT];    // [i][j] 2048
    __shared__ float b2s[H2], b3s[D_OUT], gms[D_OUT], bts[D_OUT];
    __shared__ float gws[GH * 2], gbs[2];

    const int e   = blockIdx.y;          // 0,1 shared; 2,3 group0; 4,5 group1
    const int tid = threadIdx.x;
    const int t   = blockIdx.x * 128 + tid;
    const int slot = (e < 2) ? 0 : ((e < 4) ? 1 : 2);
    const int ei   = (e < 2) ? e : ((e - 2) & 1);

    const float* w2src = (e < 2) ? (sw2 + (size_t)e * 2048) : (gw2 + (size_t)(e - 2) * 2048);
    const float* w3src = (e < 2) ? (sw3 + (size_t)e * 2048) : (gw3 + (size_t)(e - 2) * 2048);
    for (int i = tid; i < 2048; i += 128) { w2s[i] = w2src[i]; w3s[i] = w3src[i]; }
    if (tid < H2) b2s[tid] = (e < 2) ? sb2[e * 32 + tid] : gb2[(e - 2) * 32 + tid];
    if (tid < D_OUT) {
        b3s[tid] = (e < 2) ? sb3[e * 64 + tid]  : gb3[(e - 2) * 64 + tid];
        gms[tid] = (e < 2) ? sgam[e * 64 + tid] : ggam[(e - 2) * 64 + tid];
        bts[tid] = (e < 2) ? sbet[e * 64 + tid] : gbet[(e - 2) * 64 + tid];
    }
    if (tid < 64) gws[tid] = (slot == 0) ? sgw2[tid] : ggw2[(slot - 1) * 64 + tid];
    if (tid < 2)  gbs[tid] = (slot == 0) ? sgb2[tid] : ggb2[(slot - 1) * 2 + tid];
    __syncthreads();

    // layer 2: h2[32] = silu(h1 @ W2 + b2)
    float h2[H2];
#pragma unroll
    for (int j = 0; j < H2; j++) h2[j] = b2s[j];
    const float* hbase = g_HT + (size_t)e * 64 * B_TOK + t;
#pragma unroll 4
    for (int i = 0; i < H1; i++) {
        float a = hbase[(size_t)i * B_TOK];
#pragma unroll
        for (int j = 0; j < H2; j++) h2[j] += a * w2s[i * H2 + j];
    }
#pragma unroll
    for (int j = 0; j < H2; j++) h2[j] = h2[j] / (1.f + __expf(-h2[j]));

    // layer 3: o[64] = h2 @ W3 + b3
    float o[D_OUT];
#pragma unroll
    for (int j = 0; j < D_OUT; j++) o[j] = b3s[j];
#pragma unroll 2
    for (int i = 0; i < H2; i++) {
        float h = h2[i];
#pragma unroll
        for (int j = 0; j < D_OUT; j++) o[j] += h * w3s[i * D_OUT + j];
    }

    // LayerNorm (per-thread register reduction)
    float s1 = 0.f;
#pragma unroll
    for (int j = 0; j < D_OUT; j++) s1 += o[j];
    float mu = s1 * (1.f / 64.f);
    float s2 = 0.f;
#pragma unroll
    for (int j = 0; j < D_OUT; j++) { float d = o[j] - mu; s2 += d * d; }
    float x = s2 * (1.f / 64.f) + LN_EPS;
    float inv = rsqrtf(x);
    inv = inv * (1.5f - 0.5f * x * inv * inv);   // Newton refine

    // gate: softmax over 2 experts of this slot
    float l0 = gbs[0], l1 = gbs[1];
    const float* gbase = g_HT + (size_t)(384 + slot * 32) * B_TOK + t;
#pragma unroll 4
    for (int i = 0; i < GH; i++) {
        float hg = gbase[(size_t)i * B_TOK];
        l0 += hg * gws[i * 2];
        l1 += hg * gws[i * 2 + 1];
    }
    float m  = fmaxf(l0, l1);
    float e0 = __expf(l0 - m), e1 = __expf(l1 - m);
    float wg = ((ei == 0) ? e0 : e1) / (e0 + e1);

    // write gate-scaled LN output
    float* dst = g_EO + ((size_t)e * B_TOK + t) * D_OUT;
#pragma unroll
    for (int j4 = 0; j4 < D_OUT / 4; j4++) {
        float4 y;
        float* yy = (float*)&y;
#pragma unroll
        for (int u = 0; u < 4; u++) {
            int j = j4 * 4 + u;
            yy[u] = wg * (gms[j] * (o[j] - mu) * inv + bts[j]);
        }
        *(float4*)(dst + j4 * 4) = y;
    }
}

// ---------------------------------------------------------------------------
// Kernel: combine — out[p] = EO[e0] + EO[e1]; planes: 0:(2,3) 1:(4,5) 2:(0,1)
// ---------------------------------------------------------------------------
__global__ __launch_bounds__(256) void combine_kernel(float* __restrict__ out) {
    size_t gid = (size_t)blockIdx.x * 256 + threadIdx.x;   // over 3*B*16 float4
    size_t per_plane = (size_t)B_TOK * (D_OUT / 4);
    int p = (int)(gid / per_plane);
    size_t r = gid - (size_t)p * per_plane;
    int e0 = (p == 2) ? 0 : ((p == 0) ? 2 : 4);
    const float4* a = (const float4*)(g_EO + (size_t)e0 * B_TOK * D_OUT);
    const float4* b = (const float4*)(g_EO + (size_t)(e0 + 1) * B_TOK * D_OUT);
    float4 va = a[r], vb = b[r];
    float4 o = make_float4(va.x + vb.x, va.y + vb.y, va.z + vb.z, va.w + vb.w);
    ((float4*)out)[gid] = o;
}

// ---------------------------------------------------------------------------
// Launch
// ---------------------------------------------------------------------------
extern "C" void kernel_launch(void* const* d_in, const int* in_sizes, int n_in,
                              void* d_out, int out_size) {
    (void)in_sizes; (void)n_in; (void)out_size;
    const float* v    = (const float*)d_in[0];
    const float* sw1  = (const float*)d_in[1];
    const float* sb1  = (const float*)d_in[2];
    const float* sw2  = (const float*)d_in[3];
    const float* sb2  = (const float*)d_in[4];
    const float* sw3  = (const float*)d_in[5];
    const float* sb3  = (const float*)d_in[6];
    const float* sgam = (const float*)d_in[7];
    const float* sbet = (const float*)d_in[8];
    const float* sgw1 = (const float*)d_in[9];
    const float* sgb1 = (const float*)d_in[10];
    const float* sgw2 = (const float*)d_in[11];
    const float* sgb2 = (const float*)d_in[12];
    const float* gw1  = (const float*)d_in[13];
    const float* gb1  = (const float*)d_in[14];
    const float* gw2  = (const float*)d_in[15];
    const float* gb2  = (const float*)d_in[16];
    const float* gw3  = (const float*)d_in[17];
    const float* gb3  = (const float*)d_in[18];
    const float* ggam = (const float*)d_in[19];
    const float* gbet = (const float*)d_in[20];
    const float* ggw1 = (const float*)d_in[21];
    const float* ggb1 = (const float*)d_in[22];
    const float* ggw2 = (const float*)d_in[23];
    const float* ggb2 = (const float*)d_in[24];
    float* out = (float*)d_out;

    conv_v_kernel<<<(B_TOK * D_IN / 4 + 255) / 256, 256>>>(v);
    pack_w_kernel<<<(NCATP * D_IN + 255) / 256, 256>>>(sw1, sb1, gw1, gb1, sgw1, sgb1, ggw1, ggb1);

    cudaFuncSetAttribute(gemm1_mma_kernel, cudaFuncAttributeMaxDynamicSharedMemorySize, GEMM_SMEM);
    dim3 g1(NCATP / 128, B_TOK / 128);
    gemm1_mma_kernel<<<g1, 256, GEMM_SMEM>>>();

    dim3 g2(B_TOK / 128, NEXP);
    tail2_kernel<<<g2, 128>>>(sw2, sb2, sw3, sb3, sgam, sbet, sgw2, sgb2,
                              gw2, gb2, gw3, gb3, ggam, gbet, ggw2, ggb2);

    combine_kernel<<<(3 * B_TOK * (D_OUT / 4)) / 256, 256>>>(out);
}